// round 15
// baseline (speedup 1.0000x reference)
#include <cuda_runtime.h>
#include <cuda_fp16.h>
#include <stdint.h>

#define VV  128000
#define HH  2048
#define BBS 32
#define SSQ 1024
#define VT  128          // vocab rows per CTA
#define KCH 64           // K columns per chunk
#define NCH (HH / KCH)   // 32 chunks
#define CAP 4096
#define NSL 8            // slices per row in k2b/k2c

// ---------------- scratch (zero-initialized at module load; k3 re-zeroes) ----------------
__device__ float g_cand_val[BBS * CAP];
__device__ int   g_cand_idx[BBS * CAP];
__device__ int   g_cand_cnt[BBS];
__device__ float g_row_max[BBS];
__device__ float g_row_sum[BBS];
__device__ unsigned int g_max_enc[BBS];
__device__ int   g_hist[BBS * 64];
__device__ float g_psum[BBS * NSL];

// ---------------- helpers ----------------
__device__ __forceinline__ uint32_t smem_u32(const void* p) {
    uint32_t a;
    asm("{ .reg .u64 t; cvta.to.shared.u64 t, %1; cvt.u32.u64 %0, t; }" : "=r"(a) : "l"(p));
    return a;
}
__device__ __forceinline__ uint32_t pack_f16(float a, float b) {
    __half2 h = __floats2half2_rn(a, b);
    return *(uint32_t*)&h;
}
__device__ __forceinline__ void ldsm_x4(uint32_t* r, uint32_t addr) {
    asm volatile("ldmatrix.sync.aligned.m8n8.x4.shared.b16 {%0,%1,%2,%3}, [%4];"
        : "=r"(r[0]), "=r"(r[1]), "=r"(r[2]), "=r"(r[3]) : "r"(addr));
}
#define MMA(d, a, b0, b1) \
    asm volatile("mma.sync.aligned.m16n8k16.row.col.f32.f16.f16.f32 " \
        "{%0,%1,%2,%3},{%4,%5,%6,%7},{%8,%9},{%0,%1,%2,%3};" \
        : "+f"((d)[0]), "+f"((d)[1]), "+f"((d)[2]), "+f"((d)[3]) \
        : "r"((a)[0]), "r"((a)[1]), "r"((a)[2]), "r"((a)[3]), "r"(b0), "r"(b1))

// monotonic float<->uint
__device__ __forceinline__ unsigned int enc_f(float f) {
    unsigned int u = __float_as_uint(f);
    return (u & 0x80000000u) ? ~u : (u | 0x80000000u);
}
__device__ __forceinline__ float dec_f(unsigned int e) {
    unsigned int u = (e & 0x80000000u) ? (e & 0x7fffffffu) : ~e;
    return __uint_as_float(u);
}

// static smem layout: two fp16 stages + temps + warp max
#define SAS 72                   // row stride in f16 elems (144 B)
#define OA  0                    // A: 128 rows * 144 B = 18432
#define OB  18432                // B: 32 rows * 144 B = 4608
#define STG 23040                // one stage
#define OTM (2 * STG)            // 46080: temps (128 B)
#define OWM (OTM + 128)          // 46208: warp max (1024 B)
#define SMEM_K1 (OWM + 1024)     // 47232 < 48K -> static

// ---------------- K1: fp16 single-term mma.sync GEMM + softcap + temp + row max ----------------
__global__ __launch_bounds__(256, 2)
void k1_gemm(const float* __restrict__ emb, const float* __restrict__ hid,
             const int* __restrict__ posp, const float* __restrict__ temps,
             float* __restrict__ outL)
{
    __shared__ __align__(16) char smem[SMEM_K1];
    const uint32_t sb = smem_u32(smem);
    const int t = threadIdx.x, wid = t >> 5, l = t & 31;
    const int v0 = blockIdx.x * VT;
    const int pos = posp[0];

    if (t < 32) *(float*)(smem + OTM + t * 4) = temps[t];

    float d[4][4];
    #pragma unroll
    for (int i = 0; i < 4; i++)
        #pragma unroll
        for (int j = 0; j < 4; j++) d[i][j] = 0.f;

    // ldmatrix lane geometry (verified in R11/R12 passing kernels)
    const int m0 = wid * 16;
    const int arow = (l < 16) ? l : l - 16;
    const int acol = (l < 16) ? 0 : 8;
    const uint32_t aoff = ((m0 + arow) * SAS + acol) * 2;
    const int brow = (l & 7) + ((l >= 16) ? 8 : 0);
    const int bcol = (l & 8) ? 8 : 0;
    const uint32_t boff0 = (brow * SAS + bcol) * 2;
    const uint32_t boff1 = boff0 + 16 * SAS * 2;

    float4 evA[8], evB[2];
    #pragma unroll
    for (int i = 0; i < 8; i++) {
        int g = i * 256 + t, row = g >> 4, c4 = g & 15;
        evA[i] = *(const float4*)(emb + (size_t)(v0 + row) * HH + c4 * 4);
    }
    #pragma unroll
    for (int i = 0; i < 2; i++) {
        int g = i * 256 + t, row = g >> 4, c4 = g & 15;
        evB[i] = *(const float4*)(hid + ((size_t)row * SSQ + pos) * HH + c4 * 4);
    }

    for (int c = 0; c < NCH; c++) {
        char* stg = smem + (c & 1) * STG;
        const uint32_t sgb = sb + (c & 1) * STG;
        // stage A (fp16)
        #pragma unroll
        for (int i = 0; i < 8; i++) {
            int g = i * 256 + t, row = g >> 4, c4 = g & 15;
            float4 v = evA[i];
            uint32_t off = row * (SAS * 2) + c4 * 8;
            *(uint2*)(stg + OA + off) = make_uint2(pack_f16(v.x, v.y), pack_f16(v.z, v.w));
        }
        // stage B (fp16)
        #pragma unroll
        for (int i = 0; i < 2; i++) {
            int g = i * 256 + t, row = g >> 4, c4 = g & 15;
            float4 v = evB[i];
            uint32_t off = row * (SAS * 2) + c4 * 8;
            *(uint2*)(stg + OB + off) = make_uint2(pack_f16(v.x, v.y), pack_f16(v.z, v.w));
        }
        __syncthreads();
        // prefetch next chunk
        int kn = (c + 1) * KCH;
        if (kn < HH) {
            #pragma unroll
            for (int i = 0; i < 8; i++) {
                int g = i * 256 + t, row = g >> 4, c4 = g & 15;
                evA[i] = *(const float4*)(emb + (size_t)(v0 + row) * HH + kn + c4 * 4);
            }
            #pragma unroll
            for (int i = 0; i < 2; i++) {
                int g = i * 256 + t, row = g >> 4, c4 = g & 15;
                evB[i] = *(const float4*)(hid + ((size_t)row * SSQ + pos) * HH + kn + c4 * 4);
            }
        }
        // compute: 4 k16-steps, single fp16 term
        #pragma unroll
        for (int ks = 0; ks < 4; ks++) {
            uint32_t ko = ks * 32;
            uint32_t aH[4], bH0[4], bH1[4];
            ldsm_x4(aH,  sgb + OA + aoff  + ko);
            ldsm_x4(bH0, sgb + OB + boff0 + ko);
            ldsm_x4(bH1, sgb + OB + boff1 + ko);
            MMA(d[0], aH, bH0[0], bH0[1]);
            MMA(d[1], aH, bH0[2], bH0[3]);
            MMA(d[2], aH, bH1[0], bH1[1]);
            MMA(d[3], aH, bH1[2], bH1[3]);
        }
    }

    // epilogue: softcap + temperature + per-batch max
    const int g = l >> 2, tg = l & 3;
    float bm[4][2];
    #pragma unroll
    for (int nt = 0; nt < 4; nt++) {
        int b0 = nt * 8 + tg * 2;
        float t0 = *(float*)(smem + OTM + b0 * 4);
        float t1 = *(float*)(smem + OTM + (b0 + 1) * 4);
        int vlo = v0 + m0 + g, vhi = vlo + 8;
        float l00 = tanhf(d[nt][0] / 30.0f) * 30.0f / t0;
        float l10 = tanhf(d[nt][1] / 30.0f) * 30.0f / t1;
        float l01 = tanhf(d[nt][2] / 30.0f) * 30.0f / t0;
        float l11 = tanhf(d[nt][3] / 30.0f) * 30.0f / t1;
        outL[(size_t)b0 * VV + vlo]       = l00;
        outL[(size_t)(b0 + 1) * VV + vlo] = l10;
        outL[(size_t)b0 * VV + vhi]       = l01;
        outL[(size_t)(b0 + 1) * VV + vhi] = l11;
        bm[nt][0] = fmaxf(l00, l01);
        bm[nt][1] = fmaxf(l10, l11);
    }
    #pragma unroll
    for (int o = 4; o <= 16; o <<= 1)
        #pragma unroll
        for (int nt = 0; nt < 4; nt++) {
            bm[nt][0] = fmaxf(bm[nt][0], __shfl_xor_sync(0xffffffffu, bm[nt][0], o));
            bm[nt][1] = fmaxf(bm[nt][1], __shfl_xor_sync(0xffffffffu, bm[nt][1], o));
        }
    float* wmax = (float*)(smem + OWM);
    if (l < 4) {
        #pragma unroll
        for (int nt = 0; nt < 4; nt++) {
            wmax[wid * 32 + nt * 8 + l * 2]     = bm[nt][0];
            wmax[wid * 32 + nt * 8 + l * 2 + 1] = bm[nt][1];
        }
    }
    __syncthreads();
    if (t < 32) {
        float m = wmax[t];
        #pragma unroll
        for (int w = 1; w < 8; w++) m = fmaxf(m, wmax[w * 32 + t]);
        atomicMax(&g_max_enc[t], enc_f(m));
    }
}

// ---------------- k2b: sum(exp) partials + histogram (NSL slices/row) ----------------
__global__ void k2b_sum(const float* __restrict__ outL) {
    int b = blockIdx.y, sl = blockIdx.x, t = threadIdx.x;
    int wid = t >> 5, lane = t & 31;
    const int SLN = VV / 4 / NSL;   // 4000 float4 per slice
    __shared__ int wh[8 * 64];
    __shared__ float sred[8];
    for (int i = t; i < 8 * 64; i += 256) wh[i] = 0;
    __syncthreads();
    const float mx = dec_f(g_max_enc[b]);
    const float4* r4 = (const float4*)(outL + (size_t)b * VV);
    float sum = 0.f;
    for (int i = sl * SLN + t; i < (sl + 1) * SLN; i += 256) {
        float4 v = r4[i];
        sum += expf(v.x - mx) + expf(v.y - mx) + expf(v.z - mx) + expf(v.w - mx);
        atomicAdd(&wh[wid * 64 + min(63, (int)((mx - v.x) * 2.0f))], 1);
        atomicAdd(&wh[wid * 64 + min(63, (int)((mx - v.y) * 2.0f))], 1);
        atomicAdd(&wh[wid * 64 + min(63, (int)((mx - v.z) * 2.0f))], 1);
        atomicAdd(&wh[wid * 64 + min(63, (int)((mx - v.w) * 2.0f))], 1);
    }
    for (int o = 16; o; o >>= 1) sum += __shfl_xor_sync(0xffffffffu, sum, o);
    if (lane == 0) sred[wid] = sum;
    __syncthreads();
    if (t == 0) {
        float s = 0.f;
        for (int i = 0; i < 8; i++) s += sred[i];   // deterministic order
        g_psum[b * NSL + sl] = s;
    }
    if (t < 64) {
        int c = 0;
        for (int w = 0; w < 8; w++) c += wh[w * 64 + t];
        atomicAdd(&g_hist[b * 64 + t], c);
    }
}

// ---------------- k2c: threshold + candidate collection ----------------
__global__ void k2c_collect(const float* __restrict__ outL) {
    int b = blockIdx.y, sl = blockIdx.x, t = threadIdx.x;
    const int SLN = VV / 4 / NSL;
    __shared__ int s_bs;
    __shared__ float s_mx;
    if (t == 0) {
        float mx = dec_f(g_max_enc[b]);
        float S = 0.f;
        for (int i = 0; i < NSL; i++) S += g_psum[b * NSL + i];   // deterministic order
        int cum = 0, bs = 63;
        for (int i = 0; i < 64; i++) { cum += g_hist[b * 64 + i]; if (cum >= 64) { bs = i; break; } }
        s_bs = bs; s_mx = mx;
        if (sl == 0) { g_row_max[b] = mx; g_row_sum[b] = S; }
    }
    __syncthreads();
    const float mx = s_mx;
    const int bs = s_bs;
    const float4* r4 = (const float4*)(outL + (size_t)b * VV);
    for (int i = sl * SLN + t; i < (sl + 1) * SLN; i += 256) {
        float4 v = r4[i];
        float vals[4] = {v.x, v.y, v.z, v.w};
        #pragma unroll
        for (int j = 0; j < 4; j++) {
            int bin = min(63, (int)((mx - vals[j]) * 2.0f));
            if (bin <= bs) {
                int p = atomicAdd(&g_cand_cnt[b], 1);
                if (p < CAP) { g_cand_val[b * CAP + p] = vals[j]; g_cand_idx[b * CAP + p] = i * 4 + j; }
            }
        }
    }
}

// ---------------- Threefry-2x32 (JAX partitionable, key(42)) ----------------
__device__ __forceinline__ void tf_round(uint32_t &x0, uint32_t &x1, int r) {
    x0 += x1; x1 = (x1 << r) | (x1 >> (32 - r)); x1 ^= x0;
}
__device__ float gumbel_for(uint32_t n) {
    uint32_t x0 = 0u, x1 = n;
    const uint32_t k0 = 0u, k1 = 42u, k2 = 0x1BD11BDAu ^ k0 ^ k1;
    x0 += k0; x1 += k1;
    tf_round(x0,x1,13); tf_round(x0,x1,15); tf_round(x0,x1,26); tf_round(x0,x1,6);
    x0 += k1; x1 += k2 + 1u;
    tf_round(x0,x1,17); tf_round(x0,x1,29); tf_round(x0,x1,16); tf_round(x0,x1,24);
    x0 += k2; x1 += k0 + 2u;
    tf_round(x0,x1,13); tf_round(x0,x1,15); tf_round(x0,x1,26); tf_round(x0,x1,6);
    x0 += k0; x1 += k1 + 3u;
    tf_round(x0,x1,17); tf_round(x0,x1,29); tf_round(x0,x1,16); tf_round(x0,x1,24);
    x0 += k1; x1 += k2 + 4u;
    tf_round(x0,x1,13); tf_round(x0,x1,15); tf_round(x0,x1,26); tf_round(x0,x1,6);
    x0 += k2; x1 += k0 + 5u;
    uint32_t bits = x0 ^ x1;
    float u = __uint_as_float((bits >> 9) | 0x3f800000u) - 1.0f;
    u = u + 1.17549435e-38f;
    u = fmaxf(1.17549435e-38f, u);
    return -logf(-logf(u));
}

// ---------------- K3: exact fp32 recompute of candidates, rank, top-p/k, gumbel ----------------
__global__ void k3_sample(const float* __restrict__ tps, const int* __restrict__ tks,
                          const float* __restrict__ emb, const float* __restrict__ hid,
                          const int* __restrict__ posp, const float* __restrict__ temps,
                          float* __restrict__ out)
{
    const int b = blockIdx.x, tid = threadIdx.x;
    const int wid = tid >> 5, lane = tid & 31;
    __shared__ float sv[CAP];
    __shared__ int   si[CAP];
    __shared__ float tv[64];
    __shared__ int   tix[64];
    __shared__ __align__(16) float hs[HH];

    // load hidden-state row for this batch
    const int pos = posp[0];
    const float4* hrow = (const float4*)(hid + ((size_t)b * SSQ + pos) * HH);
    #pragma unroll
    for (int i = 0; i < 2; i++) ((float4*)hs)[i * 256 + tid] = hrow[i * 256 + tid];

    int n = g_cand_cnt[b]; if (n > CAP) n = CAP;
    for (int i = tid; i < n; i += 256) { si[i] = g_cand_idx[b * CAP + i]; }
    __syncthreads();

    // exact fp32 recompute: one warp per candidate
    const float temp = temps[b];
    for (int c = wid; c < n; c += 8) {
        const float4* er = (const float4*)(emb + (size_t)si[c] * HH);
        float acc = 0.f;
        #pragma unroll
        for (int j = 0; j < 16; j++) {
            float4 e = er[lane + j * 32];
            float4 h = ((const float4*)hs)[lane + j * 32];
            acc += e.x * h.x + e.y * h.y + e.z * h.z + e.w * h.w;
        }
        #pragma unroll
        for (int o = 16; o; o >>= 1) acc += __shfl_xor_sync(0xffffffffu, acc, o);
        if (lane == 0) sv[c] = tanhf(acc / 30.0f) * 30.0f / temp;
    }
    __syncthreads();

    // rank by exact (value desc, index asc) == stable argsort(-probs)
    for (int j = tid; j < n; j += 256) {
        float v = sv[j]; int id = si[j]; int r = 0;
        for (int i = 0; i < n; i++) {
            float vi = sv[i];
            if (vi > v || (vi == v && si[i] < id)) r++;
        }
        if (r < 64) { tv[r] = v; tix[r] = id; }
    }
    __syncthreads();

    if (tid == 0) {
        int m = n < 64 ? n : 64;
        float mx = g_row_max[b], S = g_row_sum[b];
        float tp = tps[b]; int kk = tks[b];
        float cum = 0.f, best = __int_as_float(0xff800000);
        int bid = 0;
        for (int j = 0; j < m; j++) {
            float p = expf(tv[j] - mx) / S;
            cum += p;
            bool keep = !((cum - p) > tp) && (j < kk);
            if (keep) {
                float sc = tv[j] + gumbel_for((uint32_t)(b * VV + tix[j]));
                if (sc > best) { best = sc; bid = tix[j]; }
            }
        }
        out[b] = (float)bid;
    }

    // reset scratch for next replay (graph-deterministic)
    __syncthreads();
    if (tid == 0) { g_cand_cnt[b] = 0; g_max_enc[b] = 0u; }
    if (tid < 64) g_hist[b * 64 + tid] = 0;
}

// ---------------- launch ----------------
extern "C" void kernel_launch(void* const* d_in, const int* in_sizes, int n_in,
                              void* d_out, int out_size)
{
    const float* emb  = (const float*)d_in[0];
    const float* hid  = (const float*)d_in[1];
    const int*   posp = (const int*)  d_in[2];
    const float* tps  = (const float*)d_in[3];
    const int*   tks  = (const int*)  d_in[4];
    const float* tmps = (const float*)d_in[5];
    float* out  = (float*)d_out;
    float* outL = out + BBS;

    k1_gemm<<<VV / VT, 256>>>(emb, hid, posp, tmps, outL);
    dim3 gs(NSL, BBS);
    k2b_sum<<<gs, 256>>>(outL);
    k2c_collect<<<gs, 256>>>(outL);
    k3_sample<<<BBS, 256>>>(tps, tks, emb, hid, posp, tmps, out);
}

// round 16
// speedup vs baseline: 1.2659x; 1.2659x over previous
#include <cuda_runtime.h>
#include <cuda_fp16.h>
#include <stdint.h>

#define VV  128000
#define HH  2048
#define BBS 32
#define SSQ 1024
#define VT  128          // vocab rows per CTA
#define KCH 64           // K columns per chunk
#define NCH (HH / KCH)   // 32 chunks
#define CAP 4096
#define NSL 16           // slices per row in k2b/k2c

// ---------------- scratch (zero-initialized at module load; k3b re-zeroes) ----------------
__device__ float g_cand_val[BBS * CAP];
__device__ int   g_cand_idx[BBS * CAP];
__device__ int   g_cand_cnt[BBS];
__device__ float g_row_max[BBS];
__device__ float g_row_sum[BBS];
__device__ unsigned int g_max_enc[BBS];
__device__ int   g_hist[BBS * 64];
__device__ float g_psum[BBS * NSL];

// ---------------- helpers ----------------
__device__ __forceinline__ uint32_t smem_u32(const void* p) {
    uint32_t a;
    asm("{ .reg .u64 t; cvta.to.shared.u64 t, %1; cvt.u32.u64 %0, t; }" : "=r"(a) : "l"(p));
    return a;
}
__device__ __forceinline__ uint32_t pack_f16(float a, float b) {
    __half2 h = __floats2half2_rn(a, b);
    return *(uint32_t*)&h;
}
__device__ __forceinline__ void ldsm_x4(uint32_t* r, uint32_t addr) {
    asm volatile("ldmatrix.sync.aligned.m8n8.x4.shared.b16 {%0,%1,%2,%3}, [%4];"
        : "=r"(r[0]), "=r"(r[1]), "=r"(r[2]), "=r"(r[3]) : "r"(addr));
}
#define MMA(d, a, b0, b1) \
    asm volatile("mma.sync.aligned.m16n8k16.row.col.f32.f16.f16.f32 " \
        "{%0,%1,%2,%3},{%4,%5,%6,%7},{%8,%9},{%0,%1,%2,%3};" \
        : "+f"((d)[0]), "+f"((d)[1]), "+f"((d)[2]), "+f"((d)[3]) \
        : "r"((a)[0]), "r"((a)[1]), "r"((a)[2]), "r"((a)[3]), "r"(b0), "r"(b1))

// monotonic float<->uint
__device__ __forceinline__ unsigned int enc_f(float f) {
    unsigned int u = __float_as_uint(f);
    return (u & 0x80000000u) ? ~u : (u | 0x80000000u);
}
__device__ __forceinline__ float dec_f(unsigned int e) {
    unsigned int u = (e & 0x80000000u) ? (e & 0x7fffffffu) : ~e;
    return __uint_as_float(u);
}

// static smem layout: two fp16 stages + temps + warp max
#define SAS 72                   // row stride in f16 elems (144 B)
#define OA  0                    // A: 128 rows * 144 B = 18432
#define OB  18432                // B: 32 rows * 144 B = 4608
#define STG 23040                // one stage
#define OTM (2 * STG)            // 46080: temps (128 B)
#define OWM (OTM + 128)          // 46208: warp max (1024 B)
#define SMEM_K1 (OWM + 1024)     // 47232 < 48K -> static

// ---------------- K1: fp16 single-term mma.sync GEMM + softcap + temp + row max ----------------
__global__ __launch_bounds__(256, 2)
void k1_gemm(const float* __restrict__ emb, const float* __restrict__ hid,
             const int* __restrict__ posp, const float* __restrict__ temps,
             float* __restrict__ outL)
{
    __shared__ __align__(16) char smem[SMEM_K1];
    const uint32_t sb = smem_u32(smem);
    const int t = threadIdx.x, wid = t >> 5, l = t & 31;
    const int v0 = blockIdx.x * VT;
    const int pos = posp[0];

    if (t < 32) *(float*)(smem + OTM + t * 4) = temps[t];

    float d[4][4];
    #pragma unroll
    for (int i = 0; i < 4; i++)
        #pragma unroll
        for (int j = 0; j < 4; j++) d[i][j] = 0.f;

    // ldmatrix lane geometry (verified R11..R15)
    const int m0 = wid * 16;
    const int arow = (l < 16) ? l : l - 16;
    const int acol = (l < 16) ? 0 : 8;
    const uint32_t aoff = ((m0 + arow) * SAS + acol) * 2;
    const int brow = (l & 7) + ((l >= 16) ? 8 : 0);
    const int bcol = (l & 8) ? 8 : 0;
    const uint32_t boff0 = (brow * SAS + bcol) * 2;
    const uint32_t boff1 = boff0 + 16 * SAS * 2;

    float4 evA[8], evB[2];
    #pragma unroll
    for (int i = 0; i < 8; i++) {
        int g = i * 256 + t, row = g >> 4, c4 = g & 15;
        evA[i] = *(const float4*)(emb + (size_t)(v0 + row) * HH + c4 * 4);
    }
    #pragma unroll
    for (int i = 0; i < 2; i++) {
        int g = i * 256 + t, row = g >> 4, c4 = g & 15;
        evB[i] = *(const float4*)(hid + ((size_t)row * SSQ + pos) * HH + c4 * 4);
    }

    for (int c = 0; c < NCH; c++) {
        char* stg = smem + (c & 1) * STG;
        const uint32_t sgb = sb + (c & 1) * STG;
        #pragma unroll
        for (int i = 0; i < 8; i++) {
            int g = i * 256 + t, row = g >> 4, c4 = g & 15;
            float4 v = evA[i];
            uint32_t off = row * (SAS * 2) + c4 * 8;
            *(uint2*)(stg + OA + off) = make_uint2(pack_f16(v.x, v.y), pack_f16(v.z, v.w));
        }
        #pragma unroll
        for (int i = 0; i < 2; i++) {
            int g = i * 256 + t, row = g >> 4, c4 = g & 15;
            float4 v = evB[i];
            uint32_t off = row * (SAS * 2) + c4 * 8;
            *(uint2*)(stg + OB + off) = make_uint2(pack_f16(v.x, v.y), pack_f16(v.z, v.w));
        }
        __syncthreads();
        int kn = (c + 1) * KCH;
        if (kn < HH) {
            #pragma unroll
            for (int i = 0; i < 8; i++) {
                int g = i * 256 + t, row = g >> 4, c4 = g & 15;
                evA[i] = *(const float4*)(emb + (size_t)(v0 + row) * HH + kn + c4 * 4);
            }
            #pragma unroll
            for (int i = 0; i < 2; i++) {
                int g = i * 256 + t, row = g >> 4, c4 = g & 15;
                evB[i] = *(const float4*)(hid + ((size_t)row * SSQ + pos) * HH + kn + c4 * 4);
            }
        }
        #pragma unroll
        for (int ks = 0; ks < 4; ks++) {
            uint32_t ko = ks * 32;
            uint32_t aH[4], bH0[4], bH1[4];
            ldsm_x4(aH,  sgb + OA + aoff  + ko);
            ldsm_x4(bH0, sgb + OB + boff0 + ko);
            ldsm_x4(bH1, sgb + OB + boff1 + ko);
            MMA(d[0], aH, bH0[0], bH0[1]);
            MMA(d[1], aH, bH0[2], bH0[3]);
            MMA(d[2], aH, bH1[0], bH1[1]);
            MMA(d[3], aH, bH1[2], bH1[3]);
        }
    }

    // epilogue: softcap + temperature + per-batch max
    const int g = l >> 2, tg = l & 3;
    float bm[4][2];
    #pragma unroll
    for (int nt = 0; nt < 4; nt++) {
        int b0 = nt * 8 + tg * 2;
        float t0 = *(float*)(smem + OTM + b0 * 4);
        float t1 = *(float*)(smem + OTM + (b0 + 1) * 4);
        int vlo = v0 + m0 + g, vhi = vlo + 8;
        float l00 = tanhf(d[nt][0] / 30.0f) * 30.0f / t0;
        float l10 = tanhf(d[nt][1] / 30.0f) * 30.0f / t1;
        float l01 = tanhf(d[nt][2] / 30.0f) * 30.0f / t0;
        float l11 = tanhf(d[nt][3] / 30.0f) * 30.0f / t1;
        outL[(size_t)b0 * VV + vlo]       = l00;
        outL[(size_t)(b0 + 1) * VV + vlo] = l10;
        outL[(size_t)b0 * VV + vhi]       = l01;
        outL[(size_t)(b0 + 1) * VV + vhi] = l11;
        bm[nt][0] = fmaxf(l00, l01);
        bm[nt][1] = fmaxf(l10, l11);
    }
    #pragma unroll
    for (int o = 4; o <= 16; o <<= 1)
        #pragma unroll
        for (int nt = 0; nt < 4; nt++) {
            bm[nt][0] = fmaxf(bm[nt][0], __shfl_xor_sync(0xffffffffu, bm[nt][0], o));
            bm[nt][1] = fmaxf(bm[nt][1], __shfl_xor_sync(0xffffffffu, bm[nt][1], o));
        }
    float* wmax = (float*)(smem + OWM);
    if (l < 4) {
        #pragma unroll
        for (int nt = 0; nt < 4; nt++) {
            wmax[wid * 32 + nt * 8 + l * 2]     = bm[nt][0];
            wmax[wid * 32 + nt * 8 + l * 2 + 1] = bm[nt][1];
        }
    }
    __syncthreads();
    if (t < 32) {
        float m = wmax[t];
        #pragma unroll
        for (int w = 1; w < 8; w++) m = fmaxf(m, wmax[w * 32 + t]);
        atomicMax(&g_max_enc[t], enc_f(m));
    }
}

// ---------------- k2b: sum(exp) partials + histogram (NSL slices/row) ----------------
__global__ void k2b_sum(const float* __restrict__ outL) {
    int b = blockIdx.y, sl = blockIdx.x, t = threadIdx.x;
    int wid = t >> 5, lane = t & 31;
    const int SLN = VV / 4 / NSL;   // 2000 float4 per slice
    __shared__ int wh[8 * 64];
    __shared__ float sred[8];
    for (int i = t; i < 8 * 64; i += 256) wh[i] = 0;
    __syncthreads();
    const float mx = dec_f(g_max_enc[b]);
    const float4* r4 = (const float4*)(outL + (size_t)b * VV);
    float sum = 0.f;
    for (int i = sl * SLN + t; i < (sl + 1) * SLN; i += 256) {
        float4 v = r4[i];
        sum += expf(v.x - mx) + expf(v.y - mx) + expf(v.z - mx) + expf(v.w - mx);
        atomicAdd(&wh[wid * 64 + min(63, (int)((mx - v.x) * 2.0f))], 1);
        atomicAdd(&wh[wid * 64 + min(63, (int)((mx - v.y) * 2.0f))], 1);
        atomicAdd(&wh[wid * 64 + min(63, (int)((mx - v.z) * 2.0f))], 1);
        atomicAdd(&wh[wid * 64 + min(63, (int)((mx - v.w) * 2.0f))], 1);
    }
    for (int o = 16; o; o >>= 1) sum += __shfl_xor_sync(0xffffffffu, sum, o);
    if (lane == 0) sred[wid] = sum;
    __syncthreads();
    if (t == 0) {
        float s = 0.f;
        for (int i = 0; i < 8; i++) s += sred[i];   // deterministic order
        g_psum[b * NSL + sl] = s;
    }
    if (t < 64) {
        int c = 0;
        for (int w = 0; w < 8; w++) c += wh[w * 64 + t];
        atomicAdd(&g_hist[b * 64 + t], c);
    }
}

// ---------------- k2c: threshold + candidate collection ----------------
__global__ void k2c_collect(const float* __restrict__ outL) {
    int b = blockIdx.y, sl = blockIdx.x, t = threadIdx.x;
    const int SLN = VV / 4 / NSL;
    __shared__ int s_bs;
    __shared__ float s_mx;
    if (t == 0) {
        float mx = dec_f(g_max_enc[b]);
        float S = 0.f;
        for (int i = 0; i < NSL; i++) S += g_psum[b * NSL + i];   // deterministic order
        int cum = 0, bs = 63;
        for (int i = 0; i < 64; i++) { cum += g_hist[b * 64 + i]; if (cum >= 64) { bs = i; break; } }
        s_bs = bs; s_mx = mx;
        if (sl == 0) { g_row_max[b] = mx; g_row_sum[b] = S; }
    }
    __syncthreads();
    const float mx = s_mx;
    const int bs = s_bs;
    const float4* r4 = (const float4*)(outL + (size_t)b * VV);
    for (int i = sl * SLN + t; i < (sl + 1) * SLN; i += 256) {
        float4 v = r4[i];
        float vals[4] = {v.x, v.y, v.z, v.w};
        #pragma unroll
        for (int j = 0; j < 4; j++) {
            int bin = min(63, (int)((mx - vals[j]) * 2.0f));
            if (bin <= bs) {
                int p = atomicAdd(&g_cand_cnt[b], 1);
                if (p < CAP) { g_cand_val[b * CAP + p] = vals[j]; g_cand_idx[b * CAP + p] = i * 4 + j; }
            }
        }
    }
}

// ---------------- k3a: exact fp32 recompute of candidates (wide parallel) ----------------
__global__ void k3a_recompute(const float* __restrict__ emb, const float* __restrict__ hid,
                              const int* __restrict__ posp, const float* __restrict__ temps)
{
    const int b = blockIdx.y, tid = threadIdx.x;
    const int wid = tid >> 5, lane = tid & 31;
    __shared__ __align__(16) float hs[HH];

    const int pos = posp[0];
    const float4* hrow = (const float4*)(hid + ((size_t)b * SSQ + pos) * HH);
    #pragma unroll
    for (int i = 0; i < 2; i++) ((float4*)hs)[i * 256 + tid] = hrow[i * 256 + tid];
    __syncthreads();

    int n = g_cand_cnt[b]; if (n > CAP) n = CAP;
    const float temp = temps[b];
    // 8 CTAs x 8 warps = 64 warps per row, candidate-strided
    for (int c = blockIdx.x * 8 + wid; c < n; c += 64) {
        const float4* er = (const float4*)(emb + (size_t)g_cand_idx[b * CAP + c] * HH);
        float acc = 0.f;
        #pragma unroll
        for (int j = 0; j < 16; j++) {
            float4 e = er[lane + j * 32];
            float4 h = ((const float4*)hs)[lane + j * 32];
            acc += e.x * h.x + e.y * h.y + e.z * h.z + e.w * h.w;
        }
        #pragma unroll
        for (int o = 16; o; o >>= 1) acc += __shfl_xor_sync(0xffffffffu, acc, o);
        if (lane == 0) g_cand_val[b * CAP + c] = tanhf(acc / 30.0f) * 30.0f / temp;
    }
}

// ---------------- Threefry-2x32 (JAX partitionable, key(42)) ----------------
__device__ __forceinline__ void tf_round(uint32_t &x0, uint32_t &x1, int r) {
    x0 += x1; x1 = (x1 << r) | (x1 >> (32 - r)); x1 ^= x0;
}
__device__ float gumbel_for(uint32_t n) {
    uint32_t x0 = 0u, x1 = n;
    const uint32_t k0 = 0u, k1 = 42u, k2 = 0x1BD11BDAu ^ k0 ^ k1;
    x0 += k0; x1 += k1;
    tf_round(x0,x1,13); tf_round(x0,x1,15); tf_round(x0,x1,26); tf_round(x0,x1,6);
    x0 += k1; x1 += k2 + 1u;
    tf_round(x0,x1,17); tf_round(x0,x1,29); tf_round(x0,x1,16); tf_round(x0,x1,24);
    x0 += k2; x1 += k0 + 2u;
    tf_round(x0,x1,13); tf_round(x0,x1,15); tf_round(x0,x1,26); tf_round(x0,x1,6);
    x0 += k0; x1 += k1 + 3u;
    tf_round(x0,x1,17); tf_round(x0,x1,29); tf_round(x0,x1,16); tf_round(x0,x1,24);
    x0 += k1; x1 += k2 + 4u;
    tf_round(x0,x1,13); tf_round(x0,x1,15); tf_round(x0,x1,26); tf_round(x0,x1,6);
    x0 += k2; x1 += k0 + 5u;
    uint32_t bits = x0 ^ x1;
    float u = __uint_as_float((bits >> 9) | 0x3f800000u) - 1.0f;
    u = u + 1.17549435e-38f;
    u = fmaxf(1.17549435e-38f, u);
    return -logf(-logf(u));
}

// ---------------- k3b: rank exact values, top-p/top-k, gumbel argmax ----------------
__global__ void k3b_sample(const float* __restrict__ tps, const int* __restrict__ tks,
                           float* __restrict__ out)
{
    const int b = blockIdx.x, tid = threadIdx.x;
    __shared__ float sv[CAP];
    __shared__ int   si[CAP];
    __shared__ float tv[64];
    __shared__ int   tix[64];

    int n = g_cand_cnt[b]; if (n > CAP) n = CAP;
    for (int i = tid; i < n; i += 256) { sv[i] = g_cand_val[b * CAP + i]; si[i] = g_cand_idx[b * CAP + i]; }
    __syncthreads();

    // rank by exact (value desc, index asc) == stable argsort(-probs)
    for (int j = tid; j < n; j += 256) {
        float v = sv[j]; int id = si[j]; int r = 0;
        for (int i = 0; i < n; i++) {
            float vi = sv[i];
            if (vi > v || (vi == v && si[i] < id)) r++;
        }
        if (r < 64) { tv[r] = v; tix[r] = id; }
    }
    __syncthreads();

    if (tid == 0) {
        int m = n < 64 ? n : 64;
        float mx = g_row_max[b], S = g_row_sum[b];
        float tp = tps[b]; int kk = tks[b];
        float cum = 0.f, best = __int_as_float(0xff800000);
        int bid = 0;
        for (int j = 0; j < m; j++) {
            float p = expf(tv[j] - mx) / S;
            cum += p;
            bool keep = !((cum - p) > tp) && (j < kk);
            if (keep) {
                float sc = tv[j] + gumbel_for((uint32_t)(b * VV + tix[j]));
                if (sc > best) { best = sc; bid = tix[j]; }
            }
        }
        out[b] = (float)bid;
    }

    // reset scratch for next replay (graph-deterministic)
    __syncthreads();
    if (tid == 0) { g_cand_cnt[b] = 0; g_max_enc[b] = 0u; }
    if (tid < 64) g_hist[b * 64 + tid] = 0;
}

// ---------------- launch ----------------
extern "C" void kernel_launch(void* const* d_in, const int* in_sizes, int n_in,
                              void* d_out, int out_size)
{
    const float* emb  = (const float*)d_in[0];
    const float* hid  = (const float*)d_in[1];
    const int*   posp = (const int*)  d_in[2];
    const float* tps  = (const float*)d_in[3];
    const int*   tks  = (const int*)  d_in[4];
    const float* tmps = (const float*)d_in[5];
    float* out  = (float*)d_out;
    float* outL = out + BBS;

    k1_gemm<<<VV / VT, 256>>>(emb, hid, posp, tmps, outL);
    dim3 gs(NSL, BBS);
    k2b_sum<<<gs, 256>>>(outL);
    k2c_collect<<<gs, 256>>>(outL);
    dim3 gr(8, BBS);
    k3a_recompute<<<gr, 256>>>(emb, hid, posp, tmps);
    k3b_sample<<<BBS, 256>>>(tps, tks, out);
}